// round 4
// baseline (speedup 1.0000x reference)
#include <cuda_runtime.h>
#include <mma.h>
#include <math.h>
#include <cstdint>

using namespace nvcuda;

#define LSEQ 32768
#define CDIM 512
#define SCH 128
#define NCHUNK (LSEQ / SCH)   // 256
#define EPS 1e-5f

#define AS_STRIDE 36
#define BS_STRIDE 132
#define EP_STRIDE 132
#define A_BYTES (128 * AS_STRIDE * 4)          // 18432
#define B_BYTES (32 * BS_STRIDE * 4)           // 16896
#define STG_BYTES (A_BYTES + B_BYTES)          // 35328
#define SMEM_TOTAL (2 * STG_BYTES)             // 70656 (>= 128*132*4 epilogue)

// ---------------- scratch (static device globals; no allocation) ----------------
__device__ float g_hidden[LSEQ * CDIM];
__device__ float g_u[LSEQ * CDIM];
__device__ float g_gate[LSEQ * CDIM];
__device__ float g_state[LSEQ * CDIM];
__device__ float g_x2[LSEQ * CDIM];
__device__ float g_h[LSEQ * CDIM];
__device__ float g_ff[LSEQ * 2 * CDIM];
__device__ float g_decay[CDIM];
__device__ float g_fend[NCHUNK * CDIM];
__device__ float g_bend[NCHUNK * CDIM];
__device__ float g_fcar[NCHUNK * CDIM];
__device__ float g_bcar[NCHUNK * CDIM];
// tf32-rounded weight copies: W_in | W_gate | W_out | W_ff1 | W_ff2
__device__ float g_wt[3 * CDIM * CDIM + 2 * CDIM * 2 * CDIM];

__device__ __forceinline__ uint32_t smem_u32(const void* p) {
    uint32_t a;
    asm("{ .reg .u64 t; cvta.to.shared.u64 t, %1; cvt.u32.u64 %0, t; }" : "=r"(a) : "l"(p));
    return a;
}

__device__ __forceinline__ float to_tf32(float x) {
    float y;
    asm("cvt.rna.tf32.f32 %0, %1;" : "=f"(y) : "f"(x));
    return y;
}

#define CP_ASYNC16(dst_u32, gptr) \
    asm volatile("cp.async.cg.shared.global [%0], [%1], 16;" :: "r"(dst_u32), "l"(gptr))
#define CP_COMMIT() asm volatile("cp.async.commit_group;" ::: "memory")
#define CP_WAIT(n)  asm volatile("cp.async.wait_group %0;" :: "n"(n) : "memory")

// ---------------- roundcopy: dst = tf32(src) ----------------
__global__ void roundcopy_kernel(const float* __restrict__ src, float* __restrict__ dst, int n4) {
    int i = blockIdx.x * blockDim.x + threadIdx.x;
    if (i < n4) {
        float4 v = ((const float4*)src)[i];
        v.x = to_tf32(v.x); v.y = to_tf32(v.y); v.z = to_tf32(v.z); v.w = to_tf32(v.w);
        ((float4*)dst)[i] = v;
    }
}

// ---------------- decay = sigmoid(logit) ----------------
__global__ void decay_kernel(const float* __restrict__ logit, float* __restrict__ decay) {
    int c = threadIdx.x;
    decay[c] = 1.0f / (1.0f + expf(-logit[c]));
}

// ---------------- LayerNorm: one warp per row; ROUND -> tf32 output ----------------
template <bool ROUND>
__global__ void ln_kernel(const float* __restrict__ x, const float* __restrict__ w,
                          const float* __restrict__ b, float* __restrict__ out) {
    int row = blockIdx.x * blockDim.y + threadIdx.y;
    int lane = threadIdx.x;
    const float4* xr = (const float4*)(x + (size_t)row * CDIM);
    float4 v[4];
    float s = 0.f, ss = 0.f;
#pragma unroll
    for (int i = 0; i < 4; i++) {
        v[i] = xr[lane + i * 32];
        s += v[i].x + v[i].y + v[i].z + v[i].w;
        ss += v[i].x * v[i].x + v[i].y * v[i].y + v[i].z * v[i].z + v[i].w * v[i].w;
    }
#pragma unroll
    for (int off = 16; off > 0; off >>= 1) {
        s += __shfl_xor_sync(0xFFFFFFFFu, s, off);
        ss += __shfl_xor_sync(0xFFFFFFFFu, ss, off);
    }
    float mu = s * (1.0f / CDIM);
    float var = ss * (1.0f / CDIM) - mu * mu;
    float rstd = rsqrtf(var + EPS);
    const float4* w4 = (const float4*)w;
    const float4* b4 = (const float4*)b;
    float4* o4 = (float4*)(out + (size_t)row * CDIM);
#pragma unroll
    for (int i = 0; i < 4; i++) {
        int idx = lane + i * 32;
        float4 wv = w4[idx], bv = b4[idx], o;
        o.x = (v[i].x - mu) * rstd * wv.x + bv.x;
        o.y = (v[i].y - mu) * rstd * wv.y + bv.y;
        o.z = (v[i].z - mu) * rstd * wv.z + bv.z;
        o.w = (v[i].w - mu) * rstd * wv.w + bv.w;
        if (ROUND) {
            o.x = to_tf32(o.x); o.y = to_tf32(o.y);
            o.z = to_tf32(o.z); o.w = to_tf32(o.w);
        }
        o4[idx] = o;
    }
}

// ---------------- TF32 wmma GEMM, cp.async double-buffered, no in-loop cvt ----------------
// Inputs A and B must already be tf32-rounded. C = epi(A@B + bias) [+ res].
// EPI: 0 = identity, 1 = sigmoid, 2 = silu.  ROUND: round output to tf32.
template <int EPI, bool ROUND>
__global__ void __launch_bounds__(256)
gemm_kernel(const float* __restrict__ A, const float* __restrict__ B,
            const float* __restrict__ bias, const float* __restrict__ res,
            float* __restrict__ Cc, int M, int N, int K) {
    extern __shared__ char smem[];
    uint32_t sb = smem_u32(smem);

    int tid = threadIdx.x;
    int w = tid >> 5;
    int wr = w & 1;        // 0..1 -> 64-row slab
    int wc = w >> 1;       // 0..3 -> 32-col slab
    int rowBase = blockIdx.y * 128;
    int nBase = blockIdx.x * 128;

    wmma::fragment<wmma::accumulator, 16, 16, 8, float> acc[4][2];
#pragma unroll
    for (int i = 0; i < 4; i++)
#pragma unroll
        for (int j = 0; j < 2; j++) wmma::fill_fragment(acc[i][j], 0.0f);

    const int T = K >> 5;

    auto load_stage = [&](int t, int s) {
        int k0 = t << 5;
        uint32_t abase = sb + s * STG_BYTES;
        uint32_t bbase = abase + A_BYTES;
#pragma unroll
        for (int p = 0; p < 4; p++) {
            int idx = tid + 256 * p;
            int row = idx >> 3;
            int c4 = (idx & 7) * 4;
            CP_ASYNC16(abase + (uint32_t)(row * AS_STRIDE + c4) * 4,
                       A + (size_t)(rowBase + row) * K + k0 + c4);
        }
#pragma unroll
        for (int p = 0; p < 4; p++) {
            int idx = tid + 256 * p;
            int kr = idx >> 5;
            int c4 = (idx & 31) * 4;
            CP_ASYNC16(bbase + (uint32_t)(kr * BS_STRIDE + c4) * 4,
                       B + (size_t)(k0 + kr) * N + nBase + c4);
        }
    };

    load_stage(0, 0);
    CP_COMMIT();

    for (int t = 0; t < T; t++) {
        int s = t & 1;
        CP_WAIT(0);
        __syncthreads();
        if (t + 1 < T) {
            load_stage(t + 1, s ^ 1);   // slot s^1 free: sync above proves t-1 compute done
            CP_COMMIT();
        }

        const float* As = (const float*)(smem + s * STG_BYTES);
        const float* Bs = (const float*)(smem + s * STG_BYTES + A_BYTES);
#pragma unroll
        for (int kk = 0; kk < 4; kk++) {
            wmma::fragment<wmma::matrix_a, 16, 16, 8, wmma::precision::tf32, wmma::row_major> a[4];
            wmma::fragment<wmma::matrix_b, 16, 16, 8, wmma::precision::tf32, wmma::row_major> bfr[2];
#pragma unroll
            for (int i = 0; i < 4; i++)
                wmma::load_matrix_sync(a[i], As + (wr * 64 + i * 16) * AS_STRIDE + kk * 8, AS_STRIDE);
#pragma unroll
            for (int j = 0; j < 2; j++)
                wmma::load_matrix_sync(bfr[j], Bs + (kk * 8) * BS_STRIDE + wc * 32 + j * 16, BS_STRIDE);
#pragma unroll
            for (int i = 0; i < 4; i++)
#pragma unroll
                for (int j = 0; j < 2; j++)
                    wmma::mma_sync(acc[i][j], a[i], bfr[j], acc[i][j]);
        }
    }
    __syncthreads();   // protect smem before epilogue reuse

    // ---- epilogue: stage 128x128 tile in smem, one vectorized pass ----
    float* ep = (float*)smem;
#pragma unroll
    for (int i = 0; i < 4; i++)
#pragma unroll
        for (int j = 0; j < 2; j++)
            wmma::store_matrix_sync(ep + (size_t)(wr * 64 + i * 16) * EP_STRIDE + wc * 32 + j * 16,
                                    acc[i][j], EP_STRIDE, wmma::mem_row_major);
    __syncthreads();

#pragma unroll
    for (int p = 0; p < 16; p++) {
        int idx = tid + 256 * p;          // 4096 float4 = 128 rows x 32 float4
        int row = idx >> 5;
        int c4 = (idx & 31) * 4;
        float4 v = *(float4*)(ep + (size_t)row * EP_STRIDE + c4);
        float4 bv = *(const float4*)(bias + nBase + c4);
        v.x += bv.x; v.y += bv.y; v.z += bv.z; v.w += bv.w;
        if (EPI == 1) {
            v.x = 1.0f / (1.0f + expf(-v.x)); v.y = 1.0f / (1.0f + expf(-v.y));
            v.z = 1.0f / (1.0f + expf(-v.z)); v.w = 1.0f / (1.0f + expf(-v.w));
        }
        if (EPI == 2) {
            v.x = v.x / (1.0f + expf(-v.x)); v.y = v.y / (1.0f + expf(-v.y));
            v.z = v.z / (1.0f + expf(-v.z)); v.w = v.w / (1.0f + expf(-v.w));
        }
        size_t goff = (size_t)(rowBase + row) * N + nBase + c4;
        if (res) {
            float4 rv = *(const float4*)(res + goff);
            v.x += rv.x; v.y += rv.y; v.z += rv.z; v.w += rv.w;
        }
        if (ROUND) {
            v.x = to_tf32(v.x); v.y = to_tf32(v.y);
            v.z = to_tf32(v.z); v.w = to_tf32(v.w);
        }
        *(float4*)(Cc + goff) = v;
    }
}

// ---------------- chunked bidirectional scan ----------------
__global__ void scan_pass1(const float* __restrict__ u, const float* __restrict__ decay,
                           float* __restrict__ fend, float* __restrict__ bend) {
    int c = threadIdx.x;
    int ch = blockIdx.x;
    float d = decay[c];
    const float* up = u + (size_t)ch * SCH * CDIM + c;
    float acc = 0.f;
#pragma unroll 8
    for (int r = 0; r < SCH; r++) acc = fmaf(d, acc, up[r * CDIM]);
    fend[ch * CDIM + c] = acc;
    acc = 0.f;
#pragma unroll 8
    for (int r = SCH - 1; r >= 0; r--) acc = fmaf(d, acc, up[r * CDIM]);
    bend[ch * CDIM + c] = acc;
}

__global__ void scan_pass2(const float* __restrict__ decay,
                           const float* __restrict__ fend, const float* __restrict__ bend,
                           float* __restrict__ fcar, float* __restrict__ bcar) {
    int c = threadIdx.x;
    float d = decay[c];
    float dS = d;
#pragma unroll
    for (int i = 0; i < 7; i++) dS = dS * dS;  // d^128
    float acc = 0.f;
#pragma unroll 4
    for (int k = 0; k < NCHUNK; k++) {
        fcar[k * CDIM + c] = acc;
        acc = fmaf(dS, acc, fend[k * CDIM + c]);
    }
    acc = 0.f;
#pragma unroll 4
    for (int k = NCHUNK - 1; k >= 0; k--) {
        bcar[k * CDIM + c] = acc;
        acc = fmaf(dS, acc, bend[k * CDIM + c]);
    }
}

// state (tf32-rounded, feeds W_out GEMM) = 0.5*(fwd+bwd)*gate
__global__ void scan_pass3(const float* __restrict__ u, const float* __restrict__ gate,
                           const float* __restrict__ decay,
                           const float* __restrict__ fcar, const float* __restrict__ bcar,
                           float* __restrict__ state) {
    int c = threadIdx.x;
    int ch = blockIdx.x;
    float d = decay[c];
    size_t off = (size_t)ch * SCH * CDIM + c;
    const float* up = u + off;
    const float* gp = gate + off;
    float* sp = state + off;
    float acc = fcar[ch * CDIM + c];
#pragma unroll 8
    for (int r = 0; r < SCH; r++) {
        acc = fmaf(d, acc, up[r * CDIM]);
        sp[r * CDIM] = acc;
    }
    acc = bcar[ch * CDIM + c];
#pragma unroll 8
    for (int r = SCH - 1; r >= 0; r--) {
        acc = fmaf(d, acc, up[r * CDIM]);
        float f = sp[r * CDIM];
        sp[r * CDIM] = to_tf32(0.5f * (f + acc) * gp[r * CDIM]);
    }
}

// ---------------- launch ----------------
extern "C" void kernel_launch(void* const* d_in, const int* in_sizes, int n_in,
                              void* d_out, int out_size) {
    const float* x       = (const float*)d_in[0];
    const float* ln1_w   = (const float*)d_in[1];
    const float* ln1_b   = (const float*)d_in[2];
    const float* W_in    = (const float*)d_in[3];
    const float* b_in    = (const float*)d_in[4];
    const float* W_gate  = (const float*)d_in[5];
    const float* b_gate  = (const float*)d_in[6];
    const float* W_out   = (const float*)d_in[7];
    const float* b_out   = (const float*)d_in[8];
    const float* dlogit  = (const float*)d_in[9];
    const float* ln2_w   = (const float*)d_in[10];
    const float* ln2_b   = (const float*)d_in[11];
    const float* W_ff1   = (const float*)d_in[12];
    const float* b_ff1   = (const float*)d_in[13];
    const float* W_ff2   = (const float*)d_in[14];
    const float* b_ff2   = (const float*)d_in[15];
    float* out = (float*)d_out;

    float *p_hidden, *p_u, *p_gate, *p_state, *p_x2, *p_h, *p_ff, *p_decay;
    float *p_fend, *p_bend, *p_fcar, *p_bcar, *p_wt;
    cudaGetSymbolAddress((void**)&p_hidden, g_hidden);
    cudaGetSymbolAddress((void**)&p_u, g_u);
    cudaGetSymbolAddress((void**)&p_gate, g_gate);
    cudaGetSymbolAddress((void**)&p_state, g_state);
    cudaGetSymbolAddress((void**)&p_x2, g_x2);
    cudaGetSymbolAddress((void**)&p_h, g_h);
    cudaGetSymbolAddress((void**)&p_ff, g_ff);
    cudaGetSymbolAddress((void**)&p_decay, g_decay);
    cudaGetSymbolAddress((void**)&p_fend, g_fend);
    cudaGetSymbolAddress((void**)&p_bend, g_bend);
    cudaGetSymbolAddress((void**)&p_fcar, g_fcar);
    cudaGetSymbolAddress((void**)&p_bcar, g_bcar);
    cudaGetSymbolAddress((void**)&p_wt, g_wt);

    float* wt_in   = p_wt;
    float* wt_gate = p_wt + CDIM * CDIM;
    float* wt_out  = p_wt + 2 * CDIM * CDIM;
    float* wt_ff1  = p_wt + 3 * CDIM * CDIM;
    float* wt_ff2  = p_wt + 3 * CDIM * CDIM + CDIM * 2 * CDIM;

    cudaFuncSetAttribute(gemm_kernel<0, false>, cudaFuncAttributeMaxDynamicSharedMemorySize, SMEM_TOTAL);
    cudaFuncSetAttribute(gemm_kernel<1, false>, cudaFuncAttributeMaxDynamicSharedMemorySize, SMEM_TOTAL);
    cudaFuncSetAttribute(gemm_kernel<2, true>,  cudaFuncAttributeMaxDynamicSharedMemorySize, SMEM_TOTAL);

    dim3 lnBlock(32, 8);
    int lnGrid = LSEQ / 8;

    // preconvert weights to tf32 copies
    {
        int n4 = CDIM * CDIM / 4;
        roundcopy_kernel<<<(n4 + 255) / 256, 256>>>(W_in, wt_in, n4);
        roundcopy_kernel<<<(n4 + 255) / 256, 256>>>(W_gate, wt_gate, n4);
        roundcopy_kernel<<<(n4 + 255) / 256, 256>>>(W_out, wt_out, n4);
        int n4b = CDIM * 2 * CDIM / 4;
        roundcopy_kernel<<<(n4b + 255) / 256, 256>>>(W_ff1, wt_ff1, n4b);
        roundcopy_kernel<<<(n4b + 255) / 256, 256>>>(W_ff2, wt_ff2, n4b);
    }

    decay_kernel<<<1, CDIM>>>(dlogit, p_decay);

    // hidden = tf32(LN1(x))
    ln_kernel<true><<<lnGrid, lnBlock>>>(x, ln1_w, ln1_b, p_hidden);

    // u = hidden @ W_in + b_in ; gate = sigmoid(hidden @ W_gate + b_gate)
    dim3 g512(CDIM / 128, LSEQ / 128);
    gemm_kernel<0, false><<<g512, 256, SMEM_TOTAL>>>(p_hidden, wt_in, b_in, nullptr, p_u, LSEQ, CDIM, CDIM);
    gemm_kernel<1, false><<<g512, 256, SMEM_TOTAL>>>(p_hidden, wt_gate, b_gate, nullptr, p_gate, LSEQ, CDIM, CDIM);

    // bidirectional scan -> state = tf32(0.5*(fwd+bwd)*gate)
    scan_pass1<<<NCHUNK, CDIM>>>(p_u, p_decay, p_fend, p_bend);
    scan_pass2<<<1, CDIM>>>(p_decay, p_fend, p_bend, p_fcar, p_bcar);
    scan_pass3<<<NCHUNK, CDIM>>>(p_u, p_gate, p_decay, p_fcar, p_bcar, p_state);

    // x2 = x + state @ W_out + b_out   (fp32 out: residual path)
    gemm_kernel<0, false><<<g512, 256, SMEM_TOTAL>>>(p_state, wt_out, b_out, x, p_x2, LSEQ, CDIM, CDIM);

    // h = tf32(LN2(x2))
    ln_kernel<true><<<lnGrid, lnBlock>>>(p_x2, ln2_w, ln2_b, p_h);

    // ff = tf32(silu(h @ W_ff1 + b_ff1))  [N = 1024]
    dim3 g1024(2 * CDIM / 128, LSEQ / 128);
    gemm_kernel<2, true><<<g1024, 256, SMEM_TOTAL>>>(p_h, wt_ff1, b_ff1, nullptr, p_ff, LSEQ, 2 * CDIM, CDIM);

    // out = x2 + ff @ W_ff2 + b_ff2  [K = 1024]
    gemm_kernel<0, false><<<g512, 256, SMEM_TOTAL>>>(p_ff, wt_ff2, b_ff2, p_x2, out, LSEQ, CDIM, 2 * CDIM);
}

// round 5
// speedup vs baseline: 1.1334x; 1.1334x over previous
#include <cuda_runtime.h>
#include <mma.h>
#include <math.h>
#include <cstdint>

using namespace nvcuda;

#define LSEQ 32768
#define CDIM 512
#define SCH 128
#define NCHUNK (LSEQ / SCH)   // 256
#define EPS 1e-5f

// GEMM tiling: block 128x256, 8 warps, warp tile 64x64
#define AS_STRIDE 36
#define BS_STRIDE 264
#define EP_STRIDE 132
#define A_BYTES (128 * AS_STRIDE * 4)          // 18432
#define B_BYTES (32 * BS_STRIDE * 4)           // 33792
#define STG_BYTES (A_BYTES + B_BYTES)          // 52224
#define SMEM_TOTAL (2 * STG_BYTES)             // 104448 (>= 128*132*4 = 67584 epilogue)

// ---------------- scratch (static device globals; no allocation) ----------------
__device__ float g_hidden[LSEQ * CDIM];
__device__ float g_u[LSEQ * CDIM];
__device__ float g_gate[LSEQ * CDIM];
__device__ float g_state[LSEQ * CDIM];
__device__ float g_x2[LSEQ * CDIM];
__device__ float g_h[LSEQ * CDIM];
__device__ float g_ff[LSEQ * 2 * CDIM];
__device__ float g_decay[CDIM];
__device__ float g_fend[NCHUNK * CDIM];
__device__ float g_bend[NCHUNK * CDIM];
__device__ float g_fcar[NCHUNK * CDIM];
__device__ float g_bcar[NCHUNK * CDIM];
// tf32-rounded weight copies: W_in | W_gate | W_out | W_ff1 | W_ff2
__device__ float g_wt[3 * CDIM * CDIM + 2 * CDIM * 2 * CDIM];

__device__ __forceinline__ uint32_t smem_u32(const void* p) {
    uint32_t a;
    asm("{ .reg .u64 t; cvta.to.shared.u64 t, %1; cvt.u32.u64 %0, t; }" : "=r"(a) : "l"(p));
    return a;
}

__device__ __forceinline__ float to_tf32(float x) {
    float y;
    asm("cvt.rna.tf32.f32 %0, %1;" : "=f"(y) : "f"(x));
    return y;
}

#define CP_ASYNC16(dst_u32, gptr) \
    asm volatile("cp.async.cg.shared.global [%0], [%1], 16;" :: "r"(dst_u32), "l"(gptr))
#define CP_COMMIT() asm volatile("cp.async.commit_group;" ::: "memory")
#define CP_WAIT(n)  asm volatile("cp.async.wait_group %0;" :: "n"(n) : "memory")

// ---------------- roundcopy: dst = tf32(src) ----------------
__global__ void roundcopy_kernel(const float* __restrict__ src, float* __restrict__ dst, int n4) {
    int i = blockIdx.x * blockDim.x + threadIdx.x;
    if (i < n4) {
        float4 v = ((const float4*)src)[i];
        v.x = to_tf32(v.x); v.y = to_tf32(v.y); v.z = to_tf32(v.z); v.w = to_tf32(v.w);
        ((float4*)dst)[i] = v;
    }
}

// ---------------- decay = sigmoid(logit) ----------------
__global__ void decay_kernel(const float* __restrict__ logit, float* __restrict__ decay) {
    int c = threadIdx.x;
    decay[c] = 1.0f / (1.0f + expf(-logit[c]));
}

// ---------------- LayerNorm: one warp per row; ROUND -> tf32 output ----------------
template <bool ROUND>
__global__ void ln_kernel(const float* __restrict__ x, const float* __restrict__ w,
                          const float* __restrict__ b, float* __restrict__ out) {
    int row = blockIdx.x * blockDim.y + threadIdx.y;
    int lane = threadIdx.x;
    const float4* xr = (const float4*)(x + (size_t)row * CDIM);
    float4 v[4];
    float s = 0.f, ss = 0.f;
#pragma unroll
    for (int i = 0; i < 4; i++) {
        v[i] = xr[lane + i * 32];
        s += v[i].x + v[i].y + v[i].z + v[i].w;
        ss += v[i].x * v[i].x + v[i].y * v[i].y + v[i].z * v[i].z + v[i].w * v[i].w;
    }
#pragma unroll
    for (int off = 16; off > 0; off >>= 1) {
        s += __shfl_xor_sync(0xFFFFFFFFu, s, off);
        ss += __shfl_xor_sync(0xFFFFFFFFu, ss, off);
    }
    float mu = s * (1.0f / CDIM);
    float var = ss * (1.0f / CDIM) - mu * mu;
    float rstd = rsqrtf(var + EPS);
    const float4* w4 = (const float4*)w;
    const float4* b4 = (const float4*)b;
    float4* o4 = (float4*)(out + (size_t)row * CDIM);
#pragma unroll
    for (int i = 0; i < 4; i++) {
        int idx = lane + i * 32;
        float4 wv = w4[idx], bv = b4[idx], o;
        o.x = (v[i].x - mu) * rstd * wv.x + bv.x;
        o.y = (v[i].y - mu) * rstd * wv.y + bv.y;
        o.z = (v[i].z - mu) * rstd * wv.z + bv.z;
        o.w = (v[i].w - mu) * rstd * wv.w + bv.w;
        if (ROUND) {
            o.x = to_tf32(o.x); o.y = to_tf32(o.y);
            o.z = to_tf32(o.z); o.w = to_tf32(o.w);
        }
        o4[idx] = o;
    }
}

// ---------------- TF32 wmma GEMM 128x256, cp.async double-buffered ----------------
// Inputs A, B pre-rounded to tf32. C = epi(A@B + bias) [+ res].
// EPI: 0 = identity, 1 = sigmoid, 2 = silu.  ROUND: round output to tf32.
template <int EPI, bool ROUND>
__global__ void __launch_bounds__(256, 1)
gemm_kernel(const float* __restrict__ A, const float* __restrict__ B,
            const float* __restrict__ bias, const float* __restrict__ res,
            float* __restrict__ Cc, int M, int N, int K) {
    extern __shared__ char smem[];
    uint32_t sb = smem_u32(smem);

    int tid = threadIdx.x;
    int w = tid >> 5;
    int wr = w & 1;        // 0..1 -> 64-row slab
    int wc = w >> 1;       // 0..3 -> 64-col slab
    int rowBase = blockIdx.y * 128;
    int nBase = blockIdx.x * 256;

    wmma::fragment<wmma::accumulator, 16, 16, 8, float> acc[4][4];
#pragma unroll
    for (int i = 0; i < 4; i++)
#pragma unroll
        for (int j = 0; j < 4; j++) wmma::fill_fragment(acc[i][j], 0.0f);

    const int T = K >> 5;

    // A tile 128x32 (stride 36), B tile 32x256 (stride 264)
    auto load_stage = [&](int t, int s) {
        int k0 = t << 5;
        uint32_t abase = sb + s * STG_BYTES;
        uint32_t bbase = abase + A_BYTES;
#pragma unroll
        for (int p = 0; p < 4; p++) {
            int idx = tid + 256 * p;
            int row = idx >> 3;
            int c4 = (idx & 7) * 4;
            CP_ASYNC16(abase + (uint32_t)(row * AS_STRIDE + c4) * 4,
                       A + (size_t)(rowBase + row) * K + k0 + c4);
        }
#pragma unroll
        for (int p = 0; p < 8; p++) {
            int idx = tid + 256 * p;
            int kr = idx >> 6;
            int c4 = (idx & 63) * 4;
            CP_ASYNC16(bbase + (uint32_t)(kr * BS_STRIDE + c4) * 4,
                       B + (size_t)(k0 + kr) * N + nBase + c4);
        }
    };

    load_stage(0, 0);
    CP_COMMIT();

    for (int t = 0; t < T; t++) {
        int s = t & 1;
        if (t + 1 < T) {
            load_stage(t + 1, s ^ 1);
            CP_COMMIT();
            CP_WAIT(1);
        } else {
            CP_WAIT(0);
        }
        __syncthreads();

        const float* As = (const float*)(smem + s * STG_BYTES);
        const float* Bs = (const float*)(smem + s * STG_BYTES + A_BYTES);
#pragma unroll
        for (int kk = 0; kk < 4; kk++) {
            wmma::fragment<wmma::matrix_a, 16, 16, 8, wmma::precision::tf32, wmma::row_major> a[4];
            wmma::fragment<wmma::matrix_b, 16, 16, 8, wmma::precision::tf32, wmma::row_major> bfr[4];
#pragma unroll
            for (int i = 0; i < 4; i++)
                wmma::load_matrix_sync(a[i], As + (wr * 64 + i * 16) * AS_STRIDE + kk * 8, AS_STRIDE);
#pragma unroll
            for (int j = 0; j < 4; j++)
                wmma::load_matrix_sync(bfr[j], Bs + (kk * 8) * BS_STRIDE + wc * 64 + j * 16, BS_STRIDE);
#pragma unroll
            for (int i = 0; i < 4; i++)
#pragma unroll
                for (int j = 0; j < 4; j++)
                    wmma::mma_sync(acc[i][j], a[i], bfr[j], acc[i][j]);
        }
        __syncthreads();
    }

    // ---- epilogue: two 128-col halves via reused smem staging ----
    float* ep = (float*)smem;
#pragma unroll
    for (int h = 0; h < 2; h++) {
        // warps whose 64-col slab lies in this half stage their fragments
        if ((wc >> 1) == h) {
            int cbase = (wc & 1) * 64;
#pragma unroll
            for (int i = 0; i < 4; i++)
#pragma unroll
                for (int j = 0; j < 4; j++)
                    wmma::store_matrix_sync(ep + (size_t)(wr * 64 + i * 16) * EP_STRIDE + cbase + j * 16,
                                            acc[i][j], EP_STRIDE, wmma::mem_row_major);
        }
        __syncthreads();

        int gc0 = nBase + h * 128;
#pragma unroll
        for (int p = 0; p < 16; p++) {
            int idx = tid + 256 * p;          // 4096 float4 = 128 rows x 32 float4
            int row = idx >> 5;
            int c4 = (idx & 31) * 4;
            float4 v = *(float4*)(ep + (size_t)row * EP_STRIDE + c4);
            float4 bv = *(const float4*)(bias + gc0 + c4);
            v.x += bv.x; v.y += bv.y; v.z += bv.z; v.w += bv.w;
            if (EPI == 1) {
                v.x = 1.0f / (1.0f + expf(-v.x)); v.y = 1.0f / (1.0f + expf(-v.y));
                v.z = 1.0f / (1.0f + expf(-v.z)); v.w = 1.0f / (1.0f + expf(-v.w));
            }
            if (EPI == 2) {
                v.x = v.x / (1.0f + expf(-v.x)); v.y = v.y / (1.0f + expf(-v.y));
                v.z = v.z / (1.0f + expf(-v.z)); v.w = v.w / (1.0f + expf(-v.w));
            }
            size_t goff = (size_t)(rowBase + row) * N + gc0 + c4;
            if (res) {
                float4 rv = *(const float4*)(res + goff);
                v.x += rv.x; v.y += rv.y; v.z += rv.z; v.w += rv.w;
            }
            if (ROUND) {
                v.x = to_tf32(v.x); v.y = to_tf32(v.y);
                v.z = to_tf32(v.z); v.w = to_tf32(v.w);
            }
            *(float4*)(Cc + goff) = v;
        }
        __syncthreads();
    }
}

// ---------------- chunked bidirectional scan ----------------
__global__ void scan_pass1(const float* __restrict__ u, const float* __restrict__ decay,
                           float* __restrict__ fend, float* __restrict__ bend) {
    int c = threadIdx.x;
    int ch = blockIdx.x;
    float d = decay[c];
    const float* up = u + (size_t)ch * SCH * CDIM + c;
    float acc = 0.f;
#pragma unroll 8
    for (int r = 0; r < SCH; r++) acc = fmaf(d, acc, up[r * CDIM]);
    fend[ch * CDIM + c] = acc;
    acc = 0.f;
#pragma unroll 8
    for (int r = SCH - 1; r >= 0; r--) acc = fmaf(d, acc, up[r * CDIM]);
    bend[ch * CDIM + c] = acc;
}

__global__ void scan_pass2(const float* __restrict__ decay,
                           const float* __restrict__ fend, const float* __restrict__ bend,
                           float* __restrict__ fcar, float* __restrict__ bcar) {
    int c = threadIdx.x;
    float d = decay[c];
    float dS = d;
#pragma unroll
    for (int i = 0; i < 7; i++) dS = dS * dS;  // d^128
    float acc = 0.f;
#pragma unroll 4
    for (int k = 0; k < NCHUNK; k++) {
        fcar[k * CDIM + c] = acc;
        acc = fmaf(dS, acc, fend[k * CDIM + c]);
    }
    acc = 0.f;
#pragma unroll 4
    for (int k = NCHUNK - 1; k >= 0; k--) {
        bcar[k * CDIM + c] = acc;
        acc = fmaf(dS, acc, bend[k * CDIM + c]);
    }
}

// state (tf32-rounded, feeds W_out GEMM) = 0.5*(fwd+bwd)*gate
__global__ void scan_pass3(const float* __restrict__ u, const float* __restrict__ gate,
                           const float* __restrict__ decay,
                           const float* __restrict__ fcar, const float* __restrict__ bcar,
                           float* __restrict__ state) {
    int c = threadIdx.x;
    int ch = blockIdx.x;
    float d = decay[c];
    size_t off = (size_t)ch * SCH * CDIM + c;
    const float* up = u + off;
    const float* gp = gate + off;
    float* sp = state + off;
    float acc = fcar[ch * CDIM + c];
#pragma unroll 8
    for (int r = 0; r < SCH; r++) {
        acc = fmaf(d, acc, up[r * CDIM]);
        sp[r * CDIM] = acc;
    }
    acc = bcar[ch * CDIM + c];
#pragma unroll 8
    for (int r = SCH - 1; r >= 0; r--) {
        acc = fmaf(d, acc, up[r * CDIM]);
        float f = sp[r * CDIM];
        sp[r * CDIM] = to_tf32(0.5f * (f + acc) * gp[r * CDIM]);
    }
}

// ---------------- launch ----------------
extern "C" void kernel_launch(void* const* d_in, const int* in_sizes, int n_in,
                              void* d_out, int out_size) {
    const float* x       = (const float*)d_in[0];
    const float* ln1_w   = (const float*)d_in[1];
    const float* ln1_b   = (const float*)d_in[2];
    const float* W_in    = (const float*)d_in[3];
    const float* b_in    = (const float*)d_in[4];
    const float* W_gate  = (const float*)d_in[5];
    const float* b_gate  = (const float*)d_in[6];
    const float* W_out   = (const float*)d_in[7];
    const float* b_out   = (const float*)d_in[8];
    const float* dlogit  = (const float*)d_in[9];
    const float* ln2_w   = (const float*)d_in[10];
    const float* ln2_b   = (const float*)d_in[11];
    const float* W_ff1   = (const float*)d_in[12];
    const float* b_ff1   = (const float*)d_in[13];
    const float* W_ff2   = (const float*)d_in[14];
    const float* b_ff2   = (const float*)d_in[15];
    float* out = (float*)d_out;

    float *p_hidden, *p_u, *p_gate, *p_state, *p_x2, *p_h, *p_ff, *p_decay;
    float *p_fend, *p_bend, *p_fcar, *p_bcar, *p_wt;
    cudaGetSymbolAddress((void**)&p_hidden, g_hidden);
    cudaGetSymbolAddress((void**)&p_u, g_u);
    cudaGetSymbolAddress((void**)&p_gate, g_gate);
    cudaGetSymbolAddress((void**)&p_state, g_state);
    cudaGetSymbolAddress((void**)&p_x2, g_x2);
    cudaGetSymbolAddress((void**)&p_h, g_h);
    cudaGetSymbolAddress((void**)&p_ff, g_ff);
    cudaGetSymbolAddress((void**)&p_decay, g_decay);
    cudaGetSymbolAddress((void**)&p_fend, g_fend);
    cudaGetSymbolAddress((void**)&p_bend, g_bend);
    cudaGetSymbolAddress((void**)&p_fcar, g_fcar);
    cudaGetSymbolAddress((void**)&p_bcar, g_bcar);
    cudaGetSymbolAddress((void**)&p_wt, g_wt);

    float* wt_in   = p_wt;
    float* wt_gate = p_wt + CDIM * CDIM;
    float* wt_out  = p_wt + 2 * CDIM * CDIM;
    float* wt_ff1  = p_wt + 3 * CDIM * CDIM;
    float* wt_ff2  = p_wt + 3 * CDIM * CDIM + CDIM * 2 * CDIM;

    cudaFuncSetAttribute(gemm_kernel<0, false>, cudaFuncAttributeMaxDynamicSharedMemorySize, SMEM_TOTAL);
    cudaFuncSetAttribute(gemm_kernel<1, false>, cudaFuncAttributeMaxDynamicSharedMemorySize, SMEM_TOTAL);
    cudaFuncSetAttribute(gemm_kernel<2, true>,  cudaFuncAttributeMaxDynamicSharedMemorySize, SMEM_TOTAL);

    dim3 lnBlock(32, 8);
    int lnGrid = LSEQ / 8;

    // preconvert weights to tf32 copies
    {
        int n4 = CDIM * CDIM / 4;
        roundcopy_kernel<<<(n4 + 255) / 256, 256>>>(W_in, wt_in, n4);
        roundcopy_kernel<<<(n4 + 255) / 256, 256>>>(W_gate, wt_gate, n4);
        roundcopy_kernel<<<(n4 + 255) / 256, 256>>>(W_out, wt_out, n4);
        int n4b = CDIM * 2 * CDIM / 4;
        roundcopy_kernel<<<(n4b + 255) / 256, 256>>>(W_ff1, wt_ff1, n4b);
        roundcopy_kernel<<<(n4b + 255) / 256, 256>>>(W_ff2, wt_ff2, n4b);
    }

    decay_kernel<<<1, CDIM>>>(dlogit, p_decay);

    // hidden = tf32(LN1(x))
    ln_kernel<true><<<lnGrid, lnBlock>>>(x, ln1_w, ln1_b, p_hidden);

    // u = hidden @ W_in + b_in ; gate = sigmoid(hidden @ W_gate + b_gate)
    dim3 g512(CDIM / 256, LSEQ / 128);
    gemm_kernel<0, false><<<g512, 256, SMEM_TOTAL>>>(p_hidden, wt_in, b_in, nullptr, p_u, LSEQ, CDIM, CDIM);
    gemm_kernel<1, false><<<g512, 256, SMEM_TOTAL>>>(p_hidden, wt_gate, b_gate, nullptr, p_gate, LSEQ, CDIM, CDIM);

    // bidirectional scan -> state = tf32(0.5*(fwd+bwd)*gate)
    scan_pass1<<<NCHUNK, CDIM>>>(p_u, p_decay, p_fend, p_bend);
    scan_pass2<<<1, CDIM>>>(p_decay, p_fend, p_bend, p_fcar, p_bcar);
    scan_pass3<<<NCHUNK, CDIM>>>(p_u, p_gate, p_decay, p_fcar, p_bcar, p_state);

    // x2 = x + state @ W_out + b_out   (fp32 out: residual path)
    gemm_kernel<0, false><<<g512, 256, SMEM_TOTAL>>>(p_state, wt_out, b_out, x, p_x2, LSEQ, CDIM, CDIM);

    // h = tf32(LN2(x2))
    ln_kernel<true><<<lnGrid, lnBlock>>>(p_x2, ln2_w, ln2_b, p_h);

    // ff = tf32(silu(h @ W_ff1 + b_ff1))  [N = 1024]
    dim3 g1024(2 * CDIM / 256, LSEQ / 128);
    gemm_kernel<2, true><<<g1024, 256, SMEM_TOTAL>>>(p_h, wt_ff1, b_ff1, nullptr, p_ff, LSEQ, 2 * CDIM, CDIM);

    // out = x2 + ff @ W_ff2 + b_ff2  [K = 1024]
    gemm_kernel<0, false><<<g512, 256, SMEM_TOTAL>>>(p_ff, wt_ff2, b_ff2, p_x2, out, LSEQ, CDIM, 2 * CDIM);
}

// round 6
// speedup vs baseline: 2.1588x; 1.9047x over previous
#include <cuda_runtime.h>
#include <cuda_bf16.h>
#include <mma.h>
#include <math.h>
#include <cstdint>

using namespace nvcuda;

#define LSEQ 32768
#define CDIM 512
#define SCH 128
#define NCHUNK (LSEQ / SCH)   // 256
#define EPS 1e-5f

// GEMM tiling: block 128x256, 8 warps, warp tile 64x64, BK=32, bf16, 4 stages
#define NSTAGE 4
#define AS_STRIDE 48            // 32 + 16 pad (bf16 elems)
#define BS_STRIDE 272           // 256 + 16 pad
#define EP_STRIDE 132
#define A_BYTES (128 * AS_STRIDE * 2)          // 12288
#define B_BYTES (32 * BS_STRIDE * 2)           // 17408
#define STG_BYTES (A_BYTES + B_BYTES)          // 29696
#define SMEM_TOTAL (NSTAGE * STG_BYTES)        // 118784 (>= 128*132*4 = 67584 epilogue)

// ---------------- scratch (static device globals; no allocation) ----------------
__device__ __nv_bfloat16 g_hidden[LSEQ * CDIM];
__device__ float         g_u[LSEQ * CDIM];
__device__ float         g_gate[LSEQ * CDIM];
__device__ __nv_bfloat16 g_state[LSEQ * CDIM];
__device__ float         g_x2[LSEQ * CDIM];
__device__ __nv_bfloat16 g_h[LSEQ * CDIM];
__device__ __nv_bfloat16 g_ff[LSEQ * 2 * CDIM];
__device__ float         g_tmp[LSEQ * CDIM];     // fwd-scan scratch (fp32)
__device__ float         g_decay[CDIM];
__device__ float         g_fend[NCHUNK * CDIM];
__device__ float         g_bend[NCHUNK * CDIM];
__device__ float         g_fcar[NCHUNK * CDIM];
__device__ float         g_bcar[NCHUNK * CDIM];
// bf16 weight copies: W_in | W_gate | W_out | W_ff1 | W_ff2
__device__ __nv_bfloat16 g_wt[3 * CDIM * CDIM + 2 * CDIM * 2 * CDIM];

__device__ __forceinline__ uint32_t smem_u32(const void* p) {
    uint32_t a;
    asm("{ .reg .u64 t; cvta.to.shared.u64 t, %1; cvt.u32.u64 %0, t; }" : "=r"(a) : "l"(p));
    return a;
}

#define CP_ASYNC16(dst_u32, gptr) \
    asm volatile("cp.async.cg.shared.global [%0], [%1], 16;" :: "r"(dst_u32), "l"(gptr))
#define CP_COMMIT() asm volatile("cp.async.commit_group;" ::: "memory")
#define CP_WAIT(n)  asm volatile("cp.async.wait_group %0;" :: "n"(n) : "memory")

// ---------------- roundcopy: bf16 weight copies ----------------
__global__ void roundcopy_kernel(const float* __restrict__ src, __nv_bfloat16* __restrict__ dst, int n4) {
    int i = blockIdx.x * blockDim.x + threadIdx.x;
    if (i < n4) {
        float4 v = ((const float4*)src)[i];
        __nv_bfloat162* d2 = (__nv_bfloat162*)dst;
        d2[i * 2]     = __floats2bfloat162_rn(v.x, v.y);
        d2[i * 2 + 1] = __floats2bfloat162_rn(v.z, v.w);
    }
}

// ---------------- decay = sigmoid(logit) ----------------
__global__ void decay_kernel(const float* __restrict__ logit, float* __restrict__ decay) {
    int c = threadIdx.x;
    decay[c] = 1.0f / (1.0f + expf(-logit[c]));
}

// ---------------- LayerNorm: one warp per row; bf16 output ----------------
__global__ void ln_kernel(const float* __restrict__ x, const float* __restrict__ w,
                          const float* __restrict__ b, __nv_bfloat16* __restrict__ out) {
    int row = blockIdx.x * blockDim.y + threadIdx.y;
    int lane = threadIdx.x;
    const float4* xr = (const float4*)(x + (size_t)row * CDIM);
    float4 v[4];
    float s = 0.f, ss = 0.f;
#pragma unroll
    for (int i = 0; i < 4; i++) {
        v[i] = xr[lane + i * 32];
        s += v[i].x + v[i].y + v[i].z + v[i].w;
        ss += v[i].x * v[i].x + v[i].y * v[i].y + v[i].z * v[i].z + v[i].w * v[i].w;
    }
#pragma unroll
    for (int off = 16; off > 0; off >>= 1) {
        s += __shfl_xor_sync(0xFFFFFFFFu, s, off);
        ss += __shfl_xor_sync(0xFFFFFFFFu, ss, off);
    }
    float mu = s * (1.0f / CDIM);
    float var = ss * (1.0f / CDIM) - mu * mu;
    float rstd = rsqrtf(var + EPS);
    const float4* w4 = (const float4*)w;
    const float4* b4 = (const float4*)b;
    __nv_bfloat162* o2 = (__nv_bfloat162*)(out + (size_t)row * CDIM);
#pragma unroll
    for (int i = 0; i < 4; i++) {
        int idx = lane + i * 32;
        float4 wv = w4[idx], bv = b4[idx];
        float ox = (v[i].x - mu) * rstd * wv.x + bv.x;
        float oy = (v[i].y - mu) * rstd * wv.y + bv.y;
        float oz = (v[i].z - mu) * rstd * wv.z + bv.z;
        float ow = (v[i].w - mu) * rstd * wv.w + bv.w;
        o2[idx * 2]     = __floats2bfloat162_rn(ox, oy);
        o2[idx * 2 + 1] = __floats2bfloat162_rn(oz, ow);
    }
}

// ---------------- bf16 wmma GEMM 128x256, 4-stage cp.async pipeline ----------------
// A: MxK bf16 row-major, B: KxN bf16 row-major. C = epi(A@B + bias) [+ res].
// EPI: 0 = identity, 1 = sigmoid, 2 = silu.  OBF16: output bf16 (else fp32).
template <int EPI, bool OBF16>
__global__ void __launch_bounds__(256, 1)
gemm_kernel(const __nv_bfloat16* __restrict__ A, const __nv_bfloat16* __restrict__ B,
            const float* __restrict__ bias, const float* __restrict__ res,
            void* __restrict__ Cout, int M, int N, int K) {
    extern __shared__ char smem[];
    uint32_t sb = smem_u32(smem);

    int tid = threadIdx.x;
    int w = tid >> 5;
    int wr = w & 1;        // 0..1 -> 64-row slab
    int wc = w >> 1;       // 0..3 -> 64-col slab
    int rowBase = blockIdx.y * 128;
    int nBase = blockIdx.x * 256;

    wmma::fragment<wmma::accumulator, 16, 16, 16, float> acc[4][4];
#pragma unroll
    for (int i = 0; i < 4; i++)
#pragma unroll
        for (int j = 0; j < 4; j++) wmma::fill_fragment(acc[i][j], 0.0f);

    const int T = K >> 5;

    // A tile 128x32 bf16 (stride 48), B tile 32x256 bf16 (stride 272)
    auto load_stage = [&](int t, int s) {
        int k0 = t << 5;
        uint32_t abase = sb + s * STG_BYTES;
        uint32_t bbase = abase + A_BYTES;
#pragma unroll
        for (int p = 0; p < 2; p++) {
            int idx = tid + 256 * p;          // 512 chunks of 8 bf16
            int row = idx >> 2;
            int c8 = (idx & 3) * 8;
            CP_ASYNC16(abase + (uint32_t)(row * AS_STRIDE + c8) * 2,
                       A + (size_t)(rowBase + row) * K + k0 + c8);
        }
#pragma unroll
        for (int p = 0; p < 4; p++) {
            int idx = tid + 256 * p;          // 1024 chunks
            int kr = idx >> 5;
            int c8 = (idx & 31) * 8;
            CP_ASYNC16(bbase + (uint32_t)(kr * BS_STRIDE + c8) * 2,
                       B + (size_t)(k0 + kr) * N + nBase + c8);
        }
    };

    // prologue: stages 0..NSTAGE-2
#pragma unroll
    for (int s = 0; s < NSTAGE - 1; s++) {
        load_stage(s, s);
        CP_COMMIT();
    }

    for (int t = 0; t < T; t++) {
        CP_WAIT(NSTAGE - 2);
        __syncthreads();
        // slot (t-1)%NSTAGE free (all warps finished compute t-1 at the sync)
        if (t + NSTAGE - 1 < T) load_stage(t + NSTAGE - 1, (t + NSTAGE - 1) % NSTAGE);
        CP_COMMIT();   // unconditional: keeps group accounting exact

        int s = t % NSTAGE;
        const __nv_bfloat16* As = (const __nv_bfloat16*)(smem + s * STG_BYTES);
        const __nv_bfloat16* Bs = (const __nv_bfloat16*)(smem + s * STG_BYTES + A_BYTES);
#pragma unroll
        for (int kk = 0; kk < 2; kk++) {
            wmma::fragment<wmma::matrix_a, 16, 16, 16, __nv_bfloat16, wmma::row_major> a[4];
            wmma::fragment<wmma::matrix_b, 16, 16, 16, __nv_bfloat16, wmma::row_major> bfr[4];
#pragma unroll
            for (int i = 0; i < 4; i++)
                wmma::load_matrix_sync(a[i], As + (wr * 64 + i * 16) * AS_STRIDE + kk * 16, AS_STRIDE);
#pragma unroll
            for (int j = 0; j < 4; j++)
                wmma::load_matrix_sync(bfr[j], Bs + (kk * 16) * BS_STRIDE + wc * 64 + j * 16, BS_STRIDE);
#pragma unroll
            for (int i = 0; i < 4; i++)
#pragma unroll
                for (int j = 0; j < 4; j++)
                    wmma::mma_sync(acc[i][j], a[i], bfr[j], acc[i][j]);
        }
    }
    __syncthreads();   // all compute done before smem reuse

    // ---- epilogue: two 128-col halves via reused smem staging ----
    float* ep = (float*)smem;
#pragma unroll
    for (int h = 0; h < 2; h++) {
        if ((wc >> 1) == h) {
            int cbase = (wc & 1) * 64;
#pragma unroll
            for (int i = 0; i < 4; i++)
#pragma unroll
                for (int j = 0; j < 4; j++)
                    wmma::store_matrix_sync(ep + (size_t)(wr * 64 + i * 16) * EP_STRIDE + cbase + j * 16,
                                            acc[i][j], EP_STRIDE, wmma::mem_row_major);
        }
        __syncthreads();

        int gc0 = nBase + h * 128;
#pragma unroll
        for (int p = 0; p < 16; p++) {
            int idx = tid + 256 * p;          // 4096 float4 = 128 rows x 32 float4
            int row = idx >> 5;
            int c4 = (idx & 31) * 4;
            float4 v = *(float4*)(ep + (size_t)row * EP_STRIDE + c4);
            float4 bv = *(const float4*)(bias + gc0 + c4);
            v.x += bv.x; v.y += bv.y; v.z += bv.z; v.w += bv.w;
            if (EPI == 1) {
                v.x = 1.0f / (1.0f + expf(-v.x)); v.y = 1.0f / (1.0f + expf(-v.y));
                v.z = 1.0f / (1.0f + expf(-v.z)); v.w = 1.0f / (1.0f + expf(-v.w));
            }
            if (EPI == 2) {
                v.x = v.x / (1.0f + expf(-v.x)); v.y = v.y / (1.0f + expf(-v.y));
                v.z = v.z / (1.0f + expf(-v.z)); v.w = v.w / (1.0f + expf(-v.w));
            }
            size_t goff = (size_t)(rowBase + row) * N + gc0 + c4;
            if (res) {
                float4 rv = *(const float4*)(res + goff);
                v.x += rv.x; v.y += rv.y; v.z += rv.z; v.w += rv.w;
            }
            if (OBF16) {
                __nv_bfloat162 p0 = __floats2bfloat162_rn(v.x, v.y);
                __nv_bfloat162 p1 = __floats2bfloat162_rn(v.z, v.w);
                __nv_bfloat162* op = (__nv_bfloat162*)((__nv_bfloat16*)Cout + goff);
                op[0] = p0; op[1] = p1;
            } else {
                *(float4*)((float*)Cout + goff) = v;
            }
        }
        __syncthreads();
    }
}

// ---------------- chunked bidirectional scan (fp32 throughout) ----------------
__global__ void scan_pass1(const float* __restrict__ u, const float* __restrict__ decay,
                           float* __restrict__ fend, float* __restrict__ bend) {
    int c = threadIdx.x;
    int ch = blockIdx.x;
    float d = decay[c];
    const float* up = u + (size_t)ch * SCH * CDIM + c;
    float acc = 0.f;
#pragma unroll 8
    for (int r = 0; r < SCH; r++) acc = fmaf(d, acc, up[r * CDIM]);
    fend[ch * CDIM + c] = acc;
    acc = 0.f;
#pragma unroll 8
    for (int r = SCH - 1; r >= 0; r--) acc = fmaf(d, acc, up[r * CDIM]);
    bend[ch * CDIM + c] = acc;
}

__global__ void scan_pass2(const float* __restrict__ decay,
                           const float* __restrict__ fend, const float* __restrict__ bend,
                           float* __restrict__ fcar, float* __restrict__ bcar) {
    int c = threadIdx.x;
    float d = decay[c];
    float dS = d;
#pragma unroll
    for (int i = 0; i < 7; i++) dS = dS * dS;  // d^128
    float acc = 0.f;
#pragma unroll 4
    for (int k = 0; k < NCHUNK; k++) {
        fcar[k * CDIM + c] = acc;
        acc = fmaf(dS, acc, fend[k * CDIM + c]);
    }
    acc = 0.f;
#pragma unroll 4
    for (int k = NCHUNK - 1; k >= 0; k--) {
        bcar[k * CDIM + c] = acc;
        acc = fmaf(dS, acc, bend[k * CDIM + c]);
    }
}

// fwd sweep -> tmp (fp32); bwd sweep combines -> state (bf16, feeds W_out GEMM)
__global__ void scan_pass3(const float* __restrict__ u, const float* __restrict__ gate,
                           const float* __restrict__ decay,
                           const float* __restrict__ fcar, const float* __restrict__ bcar,
                           float* __restrict__ tmp, __nv_bfloat16* __restrict__ state) {
    int c = threadIdx.x;
    int ch = blockIdx.x;
    float d = decay[c];
    size_t off = (size_t)ch * SCH * CDIM + c;
    const float* up = u + off;
    const float* gp = gate + off;
    float* tp = tmp + off;
    __nv_bfloat16* sp = state + off;
    float acc = fcar[ch * CDIM + c];
#pragma unroll 8
    for (int r = 0; r < SCH; r++) {
        acc = fmaf(d, acc, up[r * CDIM]);
        tp[r * CDIM] = acc;
    }
    acc = bcar[ch * CDIM + c];
#pragma unroll 8
    for (int r = SCH - 1; r >= 0; r--) {
        acc = fmaf(d, acc, up[r * CDIM]);
        sp[r * CDIM] = __float2bfloat16(0.5f * (tp[r * CDIM] + acc) * gp[r * CDIM]);
    }
}

// ---------------- launch ----------------
extern "C" void kernel_launch(void* const* d_in, const int* in_sizes, int n_in,
                              void* d_out, int out_size) {
    const float* x       = (const float*)d_in[0];
    const float* ln1_w   = (const float*)d_in[1];
    const float* ln1_b   = (const float*)d_in[2];
    const float* W_in    = (const float*)d_in[3];
    const float* b_in    = (const float*)d_in[4];
    const float* W_gate  = (const float*)d_in[5];
    const float* b_gate  = (const float*)d_in[6];
    const float* W_out   = (const float*)d_in[7];
    const float* b_out   = (const float*)d_in[8];
    const float* dlogit  = (const float*)d_in[9];
    const float* ln2_w   = (const float*)d_in[10];
    const float* ln2_b   = (const float*)d_in[11];
    const float* W_ff1   = (const float*)d_in[12];
    const float* b_ff1   = (const float*)d_in[13];
    const float* W_ff2   = (const float*)d_in[14];
    const float* b_ff2   = (const float*)d_in[15];
    float* out = (float*)d_out;

    __nv_bfloat16 *p_hidden, *p_state, *p_h, *p_ff, *p_wt;
    float *p_u, *p_gate, *p_x2, *p_tmp, *p_decay;
    float *p_fend, *p_bend, *p_fcar, *p_bcar;
    cudaGetSymbolAddress((void**)&p_hidden, g_hidden);
    cudaGetSymbolAddress((void**)&p_u, g_u);
    cudaGetSymbolAddress((void**)&p_gate, g_gate);
    cudaGetSymbolAddress((void**)&p_state, g_state);
    cudaGetSymbolAddress((void**)&p_x2, g_x2);
    cudaGetSymbolAddress((void**)&p_h, g_h);
    cudaGetSymbolAddress((void**)&p_ff, g_ff);
    cudaGetSymbolAddress((void**)&p_tmp, g_tmp);
    cudaGetSymbolAddress((void**)&p_decay, g_decay);
    cudaGetSymbolAddress((void**)&p_fend, g_fend);
    cudaGetSymbolAddress((void**)&p_bend, g_bend);
    cudaGetSymbolAddress((void**)&p_fcar, g_fcar);
    cudaGetSymbolAddress((void**)&p_bcar, g_bcar);
    cudaGetSymbolAddress((void**)&p_wt, g_wt);

    __nv_bfloat16* wt_in   = p_wt;
    __nv_bfloat16* wt_gate = p_wt + CDIM * CDIM;
    __nv_bfloat16* wt_out  = p_wt + 2 * CDIM * CDIM;
    __nv_bfloat16* wt_ff1  = p_wt + 3 * CDIM * CDIM;
    __nv_bfloat16* wt_ff2  = p_wt + 3 * CDIM * CDIM + CDIM * 2 * CDIM;

    cudaFuncSetAttribute(gemm_kernel<0, false>, cudaFuncAttributeMaxDynamicSharedMemorySize, SMEM_TOTAL);
    cudaFuncSetAttribute(gemm_kernel<1, false>, cudaFuncAttributeMaxDynamicSharedMemorySize, SMEM_TOTAL);
    cudaFuncSetAttribute(gemm_kernel<2, true>,  cudaFuncAttributeMaxDynamicSharedMemorySize, SMEM_TOTAL);

    dim3 lnBlock(32, 8);
    int lnGrid = LSEQ / 8;

    // preconvert weights to bf16 copies
    {
        int n4 = CDIM * CDIM / 4;
        roundcopy_kernel<<<(n4 + 255) / 256, 256>>>(W_in, wt_in, n4);
        roundcopy_kernel<<<(n4 + 255) / 256, 256>>>(W_gate, wt_gate, n4);
        roundcopy_kernel<<<(n4 + 255) / 256, 256>>>(W_out, wt_out, n4);
        int n4b = CDIM * 2 * CDIM / 4;
        roundcopy_kernel<<<(n4b + 255) / 256, 256>>>(W_ff1, wt_ff1, n4b);
        roundcopy_kernel<<<(n4b + 255) / 256, 256>>>(W_ff2, wt_ff2, n4b);
    }

    decay_kernel<<<1, CDIM>>>(dlogit, p_decay);

    // hidden = bf16(LN1(x))
    ln_kernel<<<lnGrid, lnBlock>>>(x, ln1_w, ln1_b, p_hidden);

    // u = hidden @ W_in + b_in ; gate = sigmoid(hidden @ W_gate + b_gate)   (fp32 outs)
    dim3 g512(CDIM / 256, LSEQ / 128);
    gemm_kernel<0, false><<<g512, 256, SMEM_TOTAL>>>(p_hidden, wt_in, b_in, nullptr, p_u, LSEQ, CDIM, CDIM);
    gemm_kernel<1, false><<<g512, 256, SMEM_TOTAL>>>(p_hidden, wt_gate, b_gate, nullptr, p_gate, LSEQ, CDIM, CDIM);

    // bidirectional scan -> state = bf16(0.5*(fwd+bwd)*gate)
    scan_pass1<<<NCHUNK, CDIM>>>(p_u, p_decay, p_fend, p_bend);
    scan_pass2<<<1, CDIM>>>(p_decay, p_fend, p_bend, p_fcar, p_bcar);
    scan_pass3<<<NCHUNK, CDIM>>>(p_u, p_gate, p_decay, p_fcar, p_bcar, p_tmp, p_state);

    // x2 = x + state @ W_out + b_out   (fp32 out)
    gemm_kernel<0, false><<<g512, 256, SMEM_TOTAL>>>(p_state, wt_out, b_out, x, p_x2, LSEQ, CDIM, CDIM);

    // h = bf16(LN2(x2))
    ln_kernel<<<lnGrid, lnBlock>>>(p_x2, ln2_w, ln2_b, p_h);

    // ff = bf16(silu(h @ W_ff1 + b_ff1))  [N = 1024]
    dim3 g1024(2 * CDIM / 256, LSEQ / 128);
    gemm_kernel<2, true><<<g1024, 256, SMEM_TOTAL>>>(p_h, wt_ff1, b_ff1, nullptr, p_ff, LSEQ, 2 * CDIM, CDIM);

    // out = x2 + ff @ W_ff2 + b_ff2  [K = 1024, fp32 out]
    gemm_kernel<0, false><<<g512, 256, SMEM_TOTAL>>>(p_ff, wt_ff2, b_ff2, p_x2, out, LSEQ, CDIM, 2 * CDIM);
}

// round 7
// speedup vs baseline: 2.3897x; 1.1070x over previous
#include <cuda_runtime.h>
#include <cuda_fp16.h>
#include <mma.h>
#include <math.h>
#include <cstdint>

using namespace nvcuda;

#define LSEQ 32768
#define CDIM 512
#define SCH 128
#define NCHUNK (LSEQ / SCH)   // 256
#define EPS 1e-5f

// GEMM tiling: block 128x256, 16 warps (512 thr), warp tile 64x32, BK=32, fp16, 4 stages
#define GTHREADS 512
#define NSTAGE 4
#define AS_STRIDE 48            // 32 + 16 pad (fp16 elems)
#define BS_STRIDE 272           // 256 + 16 pad
#define EP_STRIDE 132
#define A_BYTES (128 * AS_STRIDE * 2)          // 12288
#define B_BYTES (32 * BS_STRIDE * 2)           // 17408
#define STG_BYTES (A_BYTES + B_BYTES)          // 29696
#define SMEM_TOTAL (NSTAGE * STG_BYTES)        // 118784 (>= 128*132*4 = 67584 epilogue)

// ---------------- scratch (static device globals; no allocation) ----------------
__device__ __half g_hidden[LSEQ * CDIM];
__device__ float  g_u[LSEQ * CDIM];
__device__ float  g_gate[LSEQ * CDIM];
__device__ __half g_state[LSEQ * CDIM];
__device__ float  g_x2[LSEQ * CDIM];
__device__ __half g_h[LSEQ * CDIM];
__device__ __half g_ff[LSEQ * 2 * CDIM];
__device__ float  g_tmp[LSEQ * CDIM];     // fwd-scan scratch (fp32)
__device__ float  g_decay[CDIM];
__device__ float  g_fend[NCHUNK * CDIM];
__device__ float  g_bend[NCHUNK * CDIM];
__device__ float  g_fcar[NCHUNK * CDIM];
__device__ float  g_bcar[NCHUNK * CDIM];
// fp16 weight copies: W_in | W_gate | W_out | W_ff1 | W_ff2
__device__ __half g_wt[3 * CDIM * CDIM + 2 * CDIM * 2 * CDIM];

__device__ __forceinline__ uint32_t smem_u32(const void* p) {
    uint32_t a;
    asm("{ .reg .u64 t; cvta.to.shared.u64 t, %1; cvt.u32.u64 %0, t; }" : "=r"(a) : "l"(p));
    return a;
}

#define CP_ASYNC16(dst_u32, gptr) \
    asm volatile("cp.async.cg.shared.global [%0], [%1], 16;" :: "r"(dst_u32), "l"(gptr))
#define CP_COMMIT() asm volatile("cp.async.commit_group;" ::: "memory")
#define CP_WAIT(n)  asm volatile("cp.async.wait_group %0;" :: "n"(n) : "memory")

// ---------------- roundcopy: fp16 weight copies ----------------
__global__ void roundcopy_kernel(const float* __restrict__ src, __half* __restrict__ dst, int n4) {
    int i = blockIdx.x * blockDim.x + threadIdx.x;
    if (i < n4) {
        float4 v = ((const float4*)src)[i];
        __half2* d2 = (__half2*)dst;
        d2[i * 2]     = __floats2half2_rn(v.x, v.y);
        d2[i * 2 + 1] = __floats2half2_rn(v.z, v.w);
    }
}

// ---------------- decay = sigmoid(logit) ----------------
__global__ void decay_kernel(const float* __restrict__ logit, float* __restrict__ decay) {
    int c = threadIdx.x;
    decay[c] = 1.0f / (1.0f + expf(-logit[c]));
}

// ---------------- LayerNorm: one warp per row; fp16 output ----------------
__global__ void ln_kernel(const float* __restrict__ x, const float* __restrict__ w,
                          const float* __restrict__ b, __half* __restrict__ out) {
    int row = blockIdx.x * blockDim.y + threadIdx.y;
    int lane = threadIdx.x;
    const float4* xr = (const float4*)(x + (size_t)row * CDIM);
    float4 v[4];
    float s = 0.f, ss = 0.f;
#pragma unroll
    for (int i = 0; i < 4; i++) {
        v[i] = xr[lane + i * 32];
        s += v[i].x + v[i].y + v[i].z + v[i].w;
        ss += v[i].x * v[i].x + v[i].y * v[i].y + v[i].z * v[i].z + v[i].w * v[i].w;
    }
#pragma unroll
    for (int off = 16; off > 0; off >>= 1) {
        s += __shfl_xor_sync(0xFFFFFFFFu, s, off);
        ss += __shfl_xor_sync(0xFFFFFFFFu, ss, off);
    }
    float mu = s * (1.0f / CDIM);
    float var = ss * (1.0f / CDIM) - mu * mu;
    float rstd = rsqrtf(var + EPS);
    const float4* w4 = (const float4*)w;
    const float4* b4 = (const float4*)b;
    __half2* o2 = (__half2*)(out + (size_t)row * CDIM);
#pragma unroll
    for (int i = 0; i < 4; i++) {
        int idx = lane + i * 32;
        float4 wv = w4[idx], bv = b4[idx];
        float ox = (v[i].x - mu) * rstd * wv.x + bv.x;
        float oy = (v[i].y - mu) * rstd * wv.y + bv.y;
        float oz = (v[i].z - mu) * rstd * wv.z + bv.z;
        float ow = (v[i].w - mu) * rstd * wv.w + bv.w;
        o2[idx * 2]     = __floats2half2_rn(ox, oy);
        o2[idx * 2 + 1] = __floats2half2_rn(oz, ow);
    }
}

// ---------------- fp16 wmma GEMM 128x256, 16 warps, 4-stage cp.async ----------------
// A: MxK fp16 row-major, B: KxN fp16 row-major. C = epi(A@B + bias) [+ res].
// EPI: 0 = identity, 1 = sigmoid, 2 = silu.  OH16: output fp16 (else fp32).
template <int EPI, bool OH16>
__global__ void __launch_bounds__(GTHREADS, 1)
gemm_kernel(const __half* __restrict__ A, const __half* __restrict__ B,
            const float* __restrict__ bias, const float* __restrict__ res,
            void* __restrict__ Cout, int M, int N, int K) {
    extern __shared__ char smem[];
    uint32_t sb = smem_u32(smem);

    int tid = threadIdx.x;
    int w = tid >> 5;
    int wr = w & 1;        // 0..1  -> 64-row slab
    int wc = w >> 1;       // 0..7  -> 32-col slab
    int rowBase = blockIdx.y * 128;
    int nBase = blockIdx.x * 256;

    wmma::fragment<wmma::accumulator, 16, 16, 16, float> acc[4][2];
#pragma unroll
    for (int i = 0; i < 4; i++)
#pragma unroll
        for (int j = 0; j < 2; j++) wmma::fill_fragment(acc[i][j], 0.0f);

    const int T = K >> 5;

    // A tile 128x32 fp16 (stride 48), B tile 32x256 fp16 (stride 272)
    auto load_stage = [&](int t, int s) {
        int k0 = t << 5;
        uint32_t abase = sb + s * STG_BYTES;
        uint32_t bbase = abase + A_BYTES;
        {
            int row = tid >> 2;                // 512 chunks of 8 fp16, exactly 512 threads
            int c8 = (tid & 3) * 8;
            CP_ASYNC16(abase + (uint32_t)(row * AS_STRIDE + c8) * 2,
                       A + (size_t)(rowBase + row) * K + k0 + c8);
        }
#pragma unroll
        for (int p = 0; p < 2; p++) {
            int idx = tid + GTHREADS * p;      // 1024 chunks
            int kr = idx >> 5;
            int c8 = (idx & 31) * 8;
            CP_ASYNC16(bbase + (uint32_t)(kr * BS_STRIDE + c8) * 2,
                       B + (size_t)(k0 + kr) * N + nBase + c8);
        }
    };

    // prologue
#pragma unroll
    for (int s = 0; s < NSTAGE - 1; s++) {
        load_stage(s, s);
        CP_COMMIT();
    }

    for (int t = 0; t < T; t++) {
        CP_WAIT(NSTAGE - 2);
        __syncthreads();
        if (t + NSTAGE - 1 < T) load_stage(t + NSTAGE - 1, (t + NSTAGE - 1) % NSTAGE);
        CP_COMMIT();   // unconditional: exact group accounting

        int s = t % NSTAGE;
        const __half* As = (const __half*)(smem + s * STG_BYTES);
        const __half* Bs = (const __half*)(smem + s * STG_BYTES + A_BYTES);
#pragma unroll
        for (int kk = 0; kk < 2; kk++) {
            wmma::fragment<wmma::matrix_a, 16, 16, 16, __half, wmma::row_major> a[4];
            wmma::fragment<wmma::matrix_b, 16, 16, 16, __half, wmma::row_major> bfr[2];
#pragma unroll
            for (int i = 0; i < 4; i++)
                wmma::load_matrix_sync(a[i], As + (wr * 64 + i * 16) * AS_STRIDE + kk * 16, AS_STRIDE);
#pragma unroll
            for (int j = 0; j < 2; j++)
                wmma::load_matrix_sync(bfr[j], Bs + (kk * 16) * BS_STRIDE + wc * 32 + j * 16, BS_STRIDE);
#pragma unroll
            for (int i = 0; i < 4; i++)
#pragma unroll
                for (int j = 0; j < 2; j++)
                    wmma::mma_sync(acc[i][j], a[i], bfr[j], acc[i][j]);
        }
    }
    __syncthreads();   // all compute done before smem reuse

    // ---- epilogue: two 128-col halves via reused smem staging ----
    float* ep = (float*)smem;
#pragma unroll
    for (int h = 0; h < 2; h++) {
        if ((wc >> 2) == h) {
            int cbase = (wc & 3) * 32;
#pragma unroll
            for (int i = 0; i < 4; i++)
#pragma unroll
                for (int j = 0; j < 2; j++)
                    wmma::store_matrix_sync(ep + (size_t)(wr * 64 + i * 16) * EP_STRIDE + cbase + j * 16,
                                            acc[i][j], EP_STRIDE, wmma::mem_row_major);
        }
        __syncthreads();

        int gc0 = nBase + h * 128;
#pragma unroll
        for (int p = 0; p < 8; p++) {
            int idx = tid + GTHREADS * p;     // 4096 float4 = 128 rows x 32 float4
            int row = idx >> 5;
            int c4 = (idx & 31) * 4;
            float4 v = *(float4*)(ep + (size_t)row * EP_STRIDE + c4);
            float4 bv = *(const float4*)(bias + gc0 + c4);
            v.x += bv.x; v.y += bv.y; v.z += bv.z; v.w += bv.w;
            if (EPI == 1) {
                v.x = 1.0f / (1.0f + expf(-v.x)); v.y = 1.0f / (1.0f + expf(-v.y));
                v.z = 1.0f / (1.0f + expf(-v.z)); v.w = 1.0f / (1.0f + expf(-v.w));
            }
            if (EPI == 2) {
                v.x = v.x / (1.0f + expf(-v.x)); v.y = v.y / (1.0f + expf(-v.y));
                v.z = v.z / (1.0f + expf(-v.z)); v.w = v.w / (1.0f + expf(-v.w));
            }
            size_t goff = (size_t)(rowBase + row) * N + gc0 + c4;
            if (res) {
                float4 rv = *(const float4*)(res + goff);
                v.x += rv.x; v.y += rv.y; v.z += rv.z; v.w += rv.w;
            }
            if (OH16) {
                __half2* op = (__half2*)((__half*)Cout + goff);
                op[0] = __floats2half2_rn(v.x, v.y);
                op[1] = __floats2half2_rn(v.z, v.w);
            } else {
                *(float4*)((float*)Cout + goff) = v;
            }
        }
        __syncthreads();
    }
}

// ---------------- chunked bidirectional scan (fp32 throughout) ----------------
__global__ void scan_pass1(const float* __restrict__ u, const float* __restrict__ decay,
                           float* __restrict__ fend, float* __restrict__ bend) {
    int c = threadIdx.x;
    int ch = blockIdx.x;
    float d = decay[c];
    const float* up = u + (size_t)ch * SCH * CDIM + c;
    float acc = 0.f;
#pragma unroll 8
    for (int r = 0; r < SCH; r++) acc = fmaf(d, acc, up[r * CDIM]);
    fend[ch * CDIM + c] = acc;
    acc = 0.f;
#pragma unroll 8
    for (int r = SCH - 1; r >= 0; r--) acc = fmaf(d, acc, up[r * CDIM]);
    bend[ch * CDIM + c] = acc;
}

__global__ void scan_pass2(const float* __restrict__ decay,
                           const float* __restrict__ fend, const float* __restrict__ bend,
                           float* __restrict__ fcar, float* __restrict__ bcar) {
    int c = threadIdx.x;
    float d = decay[c];
    float dS = d;
#pragma unroll
    for (int i = 0; i < 7; i++) dS = dS * dS;  // d^128
    float acc = 0.f;
#pragma unroll 4
    for (int k = 0; k < NCHUNK; k++) {
        fcar[k * CDIM + c] = acc;
        acc = fmaf(dS, acc, fend[k * CDIM + c]);
    }
    acc = 0.f;
#pragma unroll 4
    for (int k = NCHUNK - 1; k >= 0; k--) {
        bcar[k * CDIM + c] = acc;
        acc = fmaf(dS, acc, bend[k * CDIM + c]);
    }
}

// fwd sweep -> tmp (fp32); bwd sweep combines -> state (fp16, feeds W_out GEMM)
__global__ void scan_pass3(const float* __restrict__ u, const float* __restrict__ gate,
                           const float* __restrict__ decay,
                           const float* __restrict__ fcar, const float* __restrict__ bcar,
                           float* __restrict__ tmp, __half* __restrict__ state) {
    int c = threadIdx.x;
    int ch = blockIdx.x;
    float d = decay[c];
    size_t off = (size_t)ch * SCH * CDIM + c;
    const float* up = u + off;
    const float* gp = gate + off;
    float* tp = tmp + off;
    __half* sp = state + off;
    float acc = fcar[ch * CDIM + c];
#pragma unroll 8
    for (int r = 0; r < SCH; r++) {
        acc = fmaf(d, acc, up[r * CDIM]);
        tp[r * CDIM] = acc;
    }
    acc = bcar[ch * CDIM + c];
#pragma unroll 8
    for (int r = SCH - 1; r >= 0; r--) {
        acc = fmaf(d, acc, up[r * CDIM]);
        sp[r * CDIM] = __float2half(0.5f * (tp[r * CDIM] + acc) * gp[r * CDIM]);
    }
}

// ---------------- launch ----------------
extern "C" void kernel_launch(void* const* d_in, const int* in_sizes, int n_in,
                              void* d_out, int out_size) {
    const float* x       = (const float*)d_in[0];
    const float* ln1_w   = (const float*)d_in[1];
    const float* ln1_b   = (const float*)d_in[2];
    const float* W_in    = (const float*)d_in[3];
    const float* b_in    = (const float*)d_in[4];
    const float* W_gate  = (const float*)d_in[5];
    const float* b_gate  = (const float*)d_in[6];
    const float* W_out   = (const float*)d_in[7];
    const float* b_out   = (const float*)d_in[8];
    const float* dlogit  = (const float*)d_in[9];
    const float* ln2_w   = (const float*)d_in[10];
    const float* ln2_b   = (const float*)d_in[11];
    const float* W_ff1   = (const float*)d_in[12];
    const float* b_ff1   = (const float*)d_in[13];
    const float* W_ff2   = (const float*)d_in[14];
    const float* b_ff2   = (const float*)d_in[15];
    float* out = (float*)d_out;

    __half *p_hidden, *p_state, *p_h, *p_ff, *p_wt;
    float *p_u, *p_gate, *p_x2, *p_tmp, *p_decay;
    float *p_fend, *p_bend, *p_fcar, *p_bcar;
    cudaGetSymbolAddress((void**)&p_hidden, g_hidden);
    cudaGetSymbolAddress((void**)&p_u, g_u);
    cudaGetSymbolAddress((void**)&p_gate, g_gate);
    cudaGetSymbolAddress((void**)&p_state, g_state);
    cudaGetSymbolAddress((void**)&p_x2, g_x2);
    cudaGetSymbolAddress((void**)&p_h, g_h);
    cudaGetSymbolAddress((void**)&p_ff, g_ff);
    cudaGetSymbolAddress((void**)&p_tmp, g_tmp);
    cudaGetSymbolAddress((void**)&p_decay, g_decay);
    cudaGetSymbolAddress((void**)&p_fend, g_fend);
    cudaGetSymbolAddress((void**)&p_bend, g_bend);
    cudaGetSymbolAddress((void**)&p_fcar, g_fcar);
    cudaGetSymbolAddress((void**)&p_bcar, g_bcar);
    cudaGetSymbolAddress((void**)&p_wt, g_wt);

    __half* wt_in   = p_wt;
    __half* wt_gate = p_wt + CDIM * CDIM;
    __half* wt_out  = p_wt + 2 * CDIM * CDIM;
    __half* wt_ff1  = p_wt + 3 * CDIM * CDIM;
    __half* wt_ff2  = p_wt + 3 * CDIM * CDIM + CDIM * 2 * CDIM;

    cudaFuncSetAttribute(gemm_kernel<0, false>, cudaFuncAttributeMaxDynamicSharedMemorySize, SMEM_TOTAL);
    cudaFuncSetAttribute(gemm_kernel<1, false>, cudaFuncAttributeMaxDynamicSharedMemorySize, SMEM_TOTAL);
    cudaFuncSetAttribute(gemm_kernel<2, true>,  cudaFuncAttributeMaxDynamicSharedMemorySize, SMEM_TOTAL);

    dim3 lnBlock(32, 8);
    int lnGrid = LSEQ / 8;

    // preconvert weights to fp16 copies
    {
        int n4 = CDIM * CDIM / 4;
        roundcopy_kernel<<<(n4 + 255) / 256, 256>>>(W_in, wt_in, n4);
        roundcopy_kernel<<<(n4 + 255) / 256, 256>>>(W_gate, wt_gate, n4);
        roundcopy_kernel<<<(n4 + 255) / 256, 256>>>(W_out, wt_out, n4);
        int n4b = CDIM * 2 * CDIM / 4;
        roundcopy_kernel<<<(n4b + 255) / 256, 256>>>(W_ff1, wt_ff1, n4b);
        roundcopy_kernel<<<(n4b + 255) / 256, 256>>>(W_ff2, wt_ff2, n4b);
    }

    decay_kernel<<<1, CDIM>>>(dlogit, p_decay);

    // hidden = fp16(LN1(x))
    ln_kernel<<<lnGrid, lnBlock>>>(x, ln1_w, ln1_b, p_hidden);

    // u = hidden @ W_in + b_in ; gate = sigmoid(hidden @ W_gate + b_gate)   (fp32 outs)
    dim3 g512(CDIM / 256, LSEQ / 128);
    gemm_kernel<0, false><<<g512, GTHREADS, SMEM_TOTAL>>>(p_hidden, wt_in, b_in, nullptr, p_u, LSEQ, CDIM, CDIM);
    gemm_kernel<1, false><<<g512, GTHREADS, SMEM_TOTAL>>>(p_hidden, wt_gate, b_gate, nullptr, p_gate, LSEQ, CDIM, CDIM);

    // bidirectional scan -> state = fp16(0.5*(fwd+bwd)*gate)
    scan_pass1<<<NCHUNK, CDIM>>>(p_u, p_decay, p_fend, p_bend);
    scan_pass2<<<1, CDIM>>>(p_decay, p_fend, p_bend, p_fcar, p_bcar);
    scan_pass3<<<NCHUNK, CDIM>>>(p_u, p_gate, p_decay, p_fcar, p_bcar, p_tmp, p_state);

    // x2 = x + state @ W_out + b_out   (fp32 out)
    gemm_kernel<0, false><<<g512, GTHREADS, SMEM_TOTAL>>>(p_state, wt_out, b_out, x, p_x2, LSEQ, CDIM, CDIM);

    // h = fp16(LN2(x2))
    ln_kernel<<<lnGrid, lnBlock>>>(p_x2, ln2_w, ln2_b, p_h);

    // ff = fp16(silu(h @ W_ff1 + b_ff1))  [N = 1024]
    dim3 g1024(2 * CDIM / 256, LSEQ / 128);
    gemm_kernel<2, true><<<g1024, GTHREADS, SMEM_TOTAL>>>(p_h, wt_ff1, b_ff1, nullptr, p_ff, LSEQ, 2 * CDIM, CDIM);

    // out = x2 + ff @ W_ff2 + b_ff2  [K = 1024, fp32 out]
    gemm_kernel<0, false><<<g512, GTHREADS, SMEM_TOTAL>>>(p_ff, wt_ff2, b_ff2, p_x2, out, LSEQ, CDIM, 2 * CDIM);
}